// round 16
// baseline (speedup 1.0000x reference)
#include <cuda_runtime.h>
#include <cuda_fp16.h>
#include <math.h>

#define N_NODES 50000
#define N_EDGES 1600000
#define HID 32
#define HOR 12
#define NP 8   // deg partitions

// ---------------- scratch: single zero-initialized region ----------------
#define Z_DEGP  0
#define Z_LXH   400000
#define Z_LHH   1200000
#define Z_FLAG  2000000
#define Z_TOTAL 2000004
__device__ float g_zbuf[Z_TOTAL];
__device__ float g_dinv[N_NODES];
__device__ __half g_Xsh[N_NODES * HID];   // fp16: dinv[s] * x[s]
__device__ __half g_h0sh[N_NODES * HID];  // fp16: dinv[s] * h0[s]
#define WPITCH 34
__device__ float g_WxT[256 * WPITCH];     // transposed+padded weights, smem image

#define G_DEGP  (g_zbuf + Z_DEGP)
#define G_LXH   ((__half*)(g_zbuf + Z_LXH))
#define G_LHH   ((__half*)(g_zbuf + Z_LHH))
#define G_FLAG  ((int*)(g_zbuf + Z_FLAG))

// ---------------- transpose Wx once into padded smem-image layout ----------------
__global__ void k_prep(const float* __restrict__ Wx) {
    int i = blockIdx.x * blockDim.x + threadIdx.x;   // 8192
    if (i < 8192) {
        int gm = i >> 10;
        int k  = (i >> 5) & 31;
        int j  = i & 31;
        g_WxT[(gm * 32 + j) * WPITCH + k] = Wx[i];
    }
}

// ---------------- deg partials + fused h0!=0 probe ----------------
__global__ void __launch_bounds__(256) k_deg(
        const int4* __restrict__ src4,
        const float4* __restrict__ w4,
        const float4* __restrict__ h04) {
    int i = blockIdx.x * blockDim.x + threadIdx.x;
    if (i < N_EDGES / 4) {
        int4   s = src4[i];
        float4 w = w4[i];
        float* deg = G_DEGP + (blockIdx.x & (NP - 1)) * N_NODES;
        if ((unsigned)s.x < N_NODES) atomicAdd(&deg[s.x], w.x);
        if ((unsigned)s.y < N_NODES) atomicAdd(&deg[s.y], w.y);
        if ((unsigned)s.z < N_NODES) atomicAdd(&deg[s.z], w.z);
        if ((unsigned)s.w < N_NODES) atomicAdd(&deg[s.w], w.w);
    }
    if (i < N_NODES * 8) {
        float4 v = h04[i];
        if (v.x != 0.f || v.y != 0.f || v.z != 0.f || v.w != 0.f) *G_FLAG = 1;
    }
}

// ---------------- reduce partials -> dinv + pre-scale to fp16 ----------------
__global__ void __launch_bounds__(256) k_xs(
        const float4* __restrict__ x4,
        const float4* __restrict__ h04) {
    int i = blockIdx.x * blockDim.x + threadIdx.x;
    if (i < N_NODES * 8) {
        int node = i >> 3;
        int p = i & 7;
        float part = G_DEGP[p * N_NODES + node];
        part += __shfl_xor_sync(0xffffffffu, part, 1);
        part += __shfl_xor_sync(0xffffffffu, part, 2);
        part += __shfl_xor_sync(0xffffffffu, part, 4);
        float d = part;
        float di = d > 0.f ? rsqrtf(d) : 0.f;
        if (p == 0) g_dinv[node] = di;
        float4 v = x4[i];
        __half2 a = __floats2half2_rn(v.x * di, v.y * di);
        __half2 b = __floats2half2_rn(v.z * di, v.w * di);
        uint2 pk;
        pk.x = *(unsigned*)&a; pk.y = *(unsigned*)&b;
        ((uint2*)g_Xsh)[i] = pk;
        if (*G_FLAG) {
            float4 h = h04[i];
            __half2 c = __floats2half2_rn(h.x * di, h.y * di);
            __half2 e = __floats2half2_rn(h.z * di, h.w * di);
            uint2 ph;
            ph.x = *(unsigned*)&c; ph.y = *(unsigned*)&e;
            ((uint2*)g_h0sh)[i] = ph;
        }
    }
}

// ---------------- edge aggregation: LXh[dst] += w * Xsh[src]; fp16 gather + fp16x2 RED ----------------
__global__ void __launch_bounds__(256) k_edge(
        const int* __restrict__ src,
        const int* __restrict__ dst,
        const float* __restrict__ w) {
    int lane = threadIdx.x & 31;
    long long wid = (long long)(blockIdx.x * blockDim.x + threadIdx.x) >> 5;
    long long e = wid * 32 + lane;

    int s = 0, d = 0;
    float nv = 0.f;
    if (e < N_EDGES) {
        int ss = src[e];
        int dd = dst[e];
        if ((unsigned)ss < N_NODES && (unsigned)dd < N_NODES) {
            s = ss; d = dd; nv = w[e];
        }
    }
    int hf = *G_FLAG;
    int sub = lane >> 3;
    int q   = lane & 7;
    __half* lxh = G_LXH;
    __half* lhh = G_LHH;

    #pragma unroll
    for (int it = 0; it < 8; it++) {
        int srcLane = it * 4 + sub;
        int   si  = __shfl_sync(0xffffffffu, s, srcLane);
        int   di  = __shfl_sync(0xffffffffu, d, srcLane);
        float nvi = __shfl_sync(0xffffffffu, nv, srcLane);
        if (nvi != 0.f) {
            __half2 wv = __float2half2_rn(nvi);
            uint2 raw = __ldg((const uint2*)(g_Xsh + (size_t)si * HID + q * 4));
            __half2 p0 = __hmul2(*(__half2*)&raw.x, wv);
            __half2 p1 = __hmul2(*(__half2*)&raw.y, wv);
            asm volatile("red.global.add.noftz.v2.f16x2 [%0], {%1,%2};"
                         :: "l"(lxh + (size_t)di * HID + q * 4),
                            "r"(*(unsigned*)&p0), "r"(*(unsigned*)&p1)
                         : "memory");
            if (hf) {
                uint2 rh = __ldg((const uint2*)(g_h0sh + (size_t)si * HID + q * 4));
                __half2 q0 = __hmul2(*(__half2*)&rh.x, wv);
                __half2 q1 = __hmul2(*(__half2*)&rh.y, wv);
                asm volatile("red.global.add.noftz.v2.f16x2 [%0], {%1,%2};"
                             :: "l"(lhh + (size_t)di * HID + q * 4),
                                "r"(*(unsigned*)&q0), "r"(*(unsigned*)&q1)
                             : "memory");
            }
        }
    }
}

// helpers
__device__ __forceinline__ unsigned long long ffma2(
        unsigned long long a, unsigned long long bb, unsigned long long c) {
    unsigned long long r;
    asm("fma.rn.f32x2 %0, %1, %2, %3;" : "=l"(r) : "l"(a), "l"(bb), "l"(c));
    return r;
}
__device__ __forceinline__ float fold2(unsigned long long a) {
    float lo = __uint_as_float((unsigned)(a & 0xffffffffu));
    float hi = __uint_as_float((unsigned)(a >> 32));
    return lo + hi;
}
__device__ __forceinline__ float fast_sigmoid(float x) {
    return 1.f / (1.f + __expf(-x));
}
__device__ __forceinline__ float fast_tanh(float x) {
    float e2 = __expf(2.f * x);
    return __fdividef(e2 - 1.f, e2 + 1.f);
}

// ================= FAST gates kernel (h0 == 0): 8 nodes/warp, dynamic smem =================
#define TN 64
// dynamic smem layout (floats): sWt[8704] | sU[4096] | sWl[384] | sbsum[128] | swc[96] | sbl[12]
#define SM_WT 0
#define SM_U  8704
#define SM_WL (8704 + 4096)
#define SM_BS (SM_WL + 384)
#define SM_WC (SM_BS + 128)
#define SM_BL (SM_WC + 96)
#define SM_TOT (SM_BL + 12 + 4)
__global__ void __launch_bounds__(256, 2) k_gates_fast(
        const float4* __restrict__ x4,
        const float* __restrict__ c0,
        const float* __restrict__ bx,
        const float* __restrict__ bh,
        const float* __restrict__ wc,
        const float* __restrict__ b,
        const float* __restrict__ Wl,   // [32][12]
        const float* __restrict__ bl,
        float* __restrict__ out) {
    if (*G_FLAG) return;

    extern __shared__ float sm[];
    float* sWt   = sm + SM_WT;
    float* sU    = sm + SM_U;
    float* sWl   = sm + SM_WL;
    float* sbsum = sm + SM_BS;
    float* swc   = sm + SM_WC;
    float* sbl   = sm + SM_BL;

    int tid = threadIdx.x;
    int nodeBase = blockIdx.x * TN;

    // prologue: flat float4 copy of pre-transposed weights (8704 floats = 2176 float4)
    for (int i = tid; i < 2176; i += 256)
        ((float4*)sWt)[i] = __ldg(((const float4*)g_WxT) + i);
    for (int i = tid; i < HID * HOR; i += 256) sWl[i] = Wl[i];
    if (tid < 4 * HID) sbsum[tid] = bx[tid] + bh[tid] + b[tid];
    if (tid < 3 * HID) swc[tid] = wc[tid];
    if (tid < HOR)     sbl[tid] = bl[tid];

    const uint2* lxh = (const uint2*)G_LXH;

    // stage U: 64 nodes * 16 float4 = 1024 slots
    for (int i = tid; i < TN * 16; i += 256) {
        int n = i >> 4, m = (i >> 3) & 1, kq = i & 7;
        int node = nodeBase + n;
        float4 v = make_float4(0.f, 0.f, 0.f, 0.f);
        if (node < N_NODES) {
            if (m) {
                uint2 rw = __ldg(&lxh[node * 8 + kq]);
                float2 a = __half22float2(*(__half2*)&rw.x);
                float2 bb = __half22float2(*(__half2*)&rw.y);
                float sc = -g_dinv[node];
                v = make_float4(a.x * sc, a.y * sc, bb.x * sc, bb.y * sc);
            } else {
                v = __ldg(&x4[node * 8 + kq]);
            }
        }
        ((float4*)sU)[(n * 2 + m) * 8 + kq] = v;
    }
    __syncthreads();

    int warp = tid >> 5;
    int j = tid & 31;
    int nb = warp * 8;   // 8 nodes per warp

    unsigned long long acc2[8][4];
    #pragma unroll
    for (int n = 0; n < 8; n++)
        #pragma unroll
        for (int g = 0; g < 4; g++) acc2[n][g] = 0ull;

    #pragma unroll
    for (int kk = 0; kk < 16; kk++) {
        unsigned long long wa[4], wb[4];
        #pragma unroll
        for (int g = 0; g < 4; g++) {
            wa[g] = *(const unsigned long long*)&sWt[((g * 2 + 0) * 32 + j) * WPITCH + 2 * kk];
            wb[g] = *(const unsigned long long*)&sWt[((g * 2 + 1) * 32 + j) * WPITCH + 2 * kk];
        }
        #pragma unroll
        for (int n = 0; n < 8; n++) {
            unsigned long long u0 = *(const unsigned long long*)&sU[(nb + n) * 64 + 2 * kk];
            unsigned long long u1 = *(const unsigned long long*)&sU[(nb + n) * 64 + 32 + 2 * kk];
            #pragma unroll
            for (int g = 0; g < 4; g++) {
                acc2[n][g] = ffma2(u0, wa[g], acc2[n][g]);
                acc2[n][g] = ffma2(u1, wb[g], acc2[n][g]);
            }
        }
    }

    float* oh = out;
    float* oH = out + (size_t)N_NODES * HOR;
    float* oC = oH + (size_t)N_NODES * HID;

    #pragma unroll
    for (int n = 0; n < 8; n++) {
        int node = nodeBase + nb + n;
        if (node < N_NODES) {
            float a0 = fold2(acc2[n][0]);
            float a1 = fold2(acc2[n][1]);
            float a2 = fold2(acc2[n][2]);
            float a3 = fold2(acc2[n][3]);
            float c0v = c0[node * HID + j];
            float preI = a0 + sbsum[0 * 32 + j] + swc[0 * 32 + j] * c0v;
            float preF = a1 + sbsum[1 * 32 + j] + swc[1 * 32 + j] * c0v;
            float preT = a2 + sbsum[2 * 32 + j];
            float I  = fast_sigmoid(preI);
            float Fg = fast_sigmoid(preF);
            float T  = fast_tanh(preT);
            float C  = Fg * c0v + I * T;
            float preO = a3 + sbsum[3 * 32 + j] + swc[2 * 32 + j] * C;
            float O  = fast_sigmoid(preO);
            float H  = O * fast_tanh(C);

            oH[node * HID + j] = H;
            oC[node * HID + j] = C;

            float rH = fmaxf(H, 0.f);
            float keep = 0.f;
            #pragma unroll
            for (int k = 0; k < 32; k++) {
                float rHk = __shfl_sync(0xffffffffu, rH, k);
                if (j < HOR) keep += rHk * sWl[k * HOR + j];
            }
            if (j < HOR) oh[node * HOR + j] = keep + sbl[j];
        }
    }
}

// ================= GENERIC gates kernel: only runs when h0 != 0 =================
#define GBLOCKS 592
__global__ void __launch_bounds__(256) k_gates_hf(
        const float4* __restrict__ x4,
        const float4* __restrict__ h04,
        const float* __restrict__ c0,
        const float* __restrict__ Wx,
        const float* __restrict__ bx,
        const float* __restrict__ Wh,
        const float* __restrict__ bh,
        const float* __restrict__ wc,
        const float* __restrict__ b,
        const float* __restrict__ Wl,
        const float* __restrict__ bl,
        float* __restrict__ out) {
    if (!*G_FLAG) return;

    __shared__ float sWx[8192];
    __shared__ float sU[16 * 4 * 32];
    __shared__ float sWl[HID * HOR];
    __shared__ float sbsum[4 * HID];
    __shared__ float swc[3 * HID];
    __shared__ float sbl[HOR];

    int tid = threadIdx.x;

    for (int i = tid; i < 8192; i += 256) sWx[i] = Wx[i];
    for (int i = tid; i < HID * HOR; i += 256) sWl[i] = Wl[i];
    if (tid < 4 * HID) sbsum[tid] = bx[tid] + bh[tid] + b[tid];
    if (tid < 3 * HID) swc[tid] = wc[tid];
    if (tid < HOR)     sbl[tid] = bl[tid];

    const uint2* lxh = (const uint2*)G_LXH;
    const uint2* lhh = (const uint2*)G_LHH;

    int ntiles = (N_NODES + 15) / 16;
    int warp = tid >> 5;
    int j = tid & 31;

    float* oh = out;
    float* oH = out + (size_t)N_NODES * HOR;
    float* oC = oH + (size_t)N_NODES * HID;

    for (int tile = blockIdx.x; tile < ntiles; tile += GBLOCKS) {
        int nodeBase = tile * 16;
        __syncthreads();
        for (int i = tid; i < 512; i += 256) {
            int n = i >> 5, m = (i >> 3) & 3, kq = i & 7;
            int node = nodeBase + n;
            float4 v = make_float4(0.f, 0.f, 0.f, 0.f);
            if (node < N_NODES) {
                if (m == 0) v = x4[node * 8 + kq];
                else if (m == 2) v = h04[node * 8 + kq];
                else {
                    uint2 rw = (m == 1) ? lxh[node * 8 + kq] : lhh[node * 8 + kq];
                    float2 a = __half22float2(*(__half2*)&rw.x);
                    float2 bb = __half22float2(*(__half2*)&rw.y);
                    float sc = -g_dinv[node];
                    v = make_float4(a.x * sc, a.y * sc, bb.x * sc, bb.y * sc);
                }
            }
            ((float4*)sU)[(n * 4 + m) * 8 + kq] = v;
        }
        __syncthreads();

        float acc[2][4];
        #pragma unroll
        for (int n = 0; n < 2; n++)
            #pragma unroll
            for (int g = 0; g < 4; g++) acc[n][g] = 0.f;

        int nb = warp * 2;
        #pragma unroll
        for (int k = 0; k < 32; k++) {
            float wa[4], wb[4], wha[4], whb[4];
            #pragma unroll
            for (int g = 0; g < 4; g++) {
                wa[g]  = sWx[g * 2048 +        k * 32 + j];
                wb[g]  = sWx[g * 2048 + 1024 + k * 32 + j];
                wha[g] = __ldg(&Wh[g * 2048 +        k * 32 + j]);
                whb[g] = __ldg(&Wh[g * 2048 + 1024 + k * 32 + j]);
            }
            #pragma unroll
            for (int n = 0; n < 2; n++) {
                float xv  = sU[((nb + n) * 4 + 0) * 32 + k];
                float lxv = sU[((nb + n) * 4 + 1) * 32 + k];
                float hv  = sU[((nb + n) * 4 + 2) * 32 + k];
                float lhv = sU[((nb + n) * 4 + 3) * 32 + k];
                #pragma unroll
                for (int g = 0; g < 4; g++)
                    acc[n][g] += xv * wa[g] + lxv * wb[g] + hv * wha[g] + lhv * whb[g];
            }
        }

        #pragma unroll
        for (int n = 0; n < 2; n++) {
            int node = nodeBase + nb + n;
            if (node < N_NODES) {
                float c0v = c0[node * HID + j];
                float preI = acc[n][0] + sbsum[0 * 32 + j] + swc[0 * 32 + j] * c0v;
                float preF = acc[n][1] + sbsum[1 * 32 + j] + swc[1 * 32 + j] * c0v;
                float preT = acc[n][2] + sbsum[2 * 32 + j];
                float I  = 1.f / (1.f + __expf(-preI));
                float Fg = 1.f / (1.f + __expf(-preF));
                float T  = tanhf(preT);
                float C  = Fg * c0v + I * T;
                float preO = acc[n][3] + sbsum[3 * 32 + j] + swc[2 * 32 + j] * C;
                float O  = 1.f / (1.f + __expf(-preO));
                float H  = O * tanhf(C);

                oH[node * HID + j] = H;
                oC[node * HID + j] = C;

                float rH = fmaxf(H, 0.f);
                float keep = 0.f;
                #pragma unroll
                for (int k = 0; k < 32; k++) {
                    float rHk = __shfl_sync(0xffffffffu, rH, k);
                    if (j < HOR) keep += rHk * sWl[k * HOR + j];
                }
                if (j < HOR) oh[node * HOR + j] = keep + sbl[j];
            }
        }
    }
}

// ---------------- launch ----------------
extern "C" void kernel_launch(void* const* d_in, const int* in_sizes, int n_in,
                              void* d_out, int out_size) {
    int iX, iEI, iEW, iWx, iBx, iWh, iBh, iWc, iB, iWl, iBl, iH0, iC0;
    if (n_in > 8 && in_sizes[8] == 2 * N_EDGES) {
        iWl = 0; iWh = 1; iWx = 2; iB = 3; iBl = 4; iBh = 5; iBx = 6;
        iC0 = 7; iEI = 8; iEW = 9; iH0 = 10; iWc = 11; iX = 12;
    } else {
        iX = 0; iEI = 1; iEW = 2; iWx = 3; iBx = 4; iWh = 5; iBh = 6;
        iWc = 7; iB = 8; iWl = 9; iBl = 10; iH0 = 11; iC0 = 12;
    }

    const float* x    = (const float*)d_in[iX];
    const int*   ei   = (const int*)d_in[iEI];     // int32 (JAX x64 off)
    const float* ew   = (const float*)d_in[iEW];
    const float* Wx   = (const float*)d_in[iWx];
    const float* bx   = (const float*)d_in[iBx];
    const float* Wh   = (const float*)d_in[iWh];
    const float* bh   = (const float*)d_in[iBh];
    const float* wc   = (const float*)d_in[iWc];
    const float* b    = (const float*)d_in[iB];
    const float* Wl   = (const float*)d_in[iWl];
    const float* bl   = (const float*)d_in[iBl];
    const float* h0   = (const float*)d_in[iH0];
    const float* c0   = (const float*)d_in[iC0];
    float*       out  = (float*)d_out;

    const int* src = ei;
    const int* dst = ei + N_EDGES;

    size_t smemBytes = SM_TOT * sizeof(float);   // ~54 KB
    cudaFuncSetAttribute(k_gates_fast,
                         cudaFuncAttributeMaxDynamicSharedMemorySize, (int)smemBytes);
    cudaFuncSetAttribute(k_gates_fast,
                         cudaFuncAttributePreferredSharedMemoryCarveout, 100);

    void* pZ;
    cudaGetSymbolAddress(&pZ, g_zbuf);
    cudaMemsetAsync(pZ, 0, Z_TOTAL * sizeof(float));

    k_prep<<<32, 256>>>(Wx);

    k_deg<<<(N_EDGES / 4 + 255) / 256, 256>>>(
        (const int4*)src, (const float4*)ew, (const float4*)h0);

    k_xs<<<(N_NODES * 8 + 255) / 256, 256>>>(
        (const float4*)x, (const float4*)h0);

    long long warps = (N_EDGES + 31) / 32;
    k_edge<<<(int)((warps * 32 + 255) / 256), 256>>>(src, dst, ew);

    k_gates_fast<<<(N_NODES + TN - 1) / TN, 256, smemBytes>>>(
        (const float4*)x, c0, bx, bh, wc, b, Wl, bl, out);
    k_gates_hf<<<GBLOCKS, 256>>>(
        (const float4*)x, (const float4*)h0, c0,
        Wx, bx, Wh, bh, wc, b, Wl, bl, out);
}

// round 17
// speedup vs baseline: 1.1214x; 1.1214x over previous
#include <cuda_runtime.h>
#include <cuda_fp16.h>
#include <math.h>

#define N_NODES 50000
#define N_EDGES 1600000
#define HID 32
#define HOR 12
#define NP 8   // deg partitions

// ---------------- scratch: single zero-initialized region ----------------
#define Z_DEGP  0
#define Z_LXH   400000
#define Z_LHH   1200000
#define Z_FLAG  2000000
#define Z_TOTAL 2000004
__device__ float g_zbuf[Z_TOTAL];
__device__ float g_dinv[N_NODES];
__device__ __half g_Xsh[N_NODES * HID];   // fp16: dinv[s] * x[s]
__device__ __half g_h0sh[N_NODES * HID];  // fp16: dinv[s] * h0[s]
#define WPITCH 34
__device__ float g_WxT[256 * WPITCH];     // transposed+padded weights, exact smem image

#define G_DEGP  (g_zbuf + Z_DEGP)
#define G_LXH   ((__half*)(g_zbuf + Z_LXH))
#define G_LHH   ((__half*)(g_zbuf + Z_LHH))
#define G_FLAG  ((int*)(g_zbuf + Z_FLAG))

// ---------------- transpose Wx once into padded smem-image layout ----------------
__global__ void k_prep(const float* __restrict__ Wx) {
    int i = blockIdx.x * blockDim.x + threadIdx.x;   // 8192
    if (i < 8192) {
        int gm = i >> 10;
        int k  = (i >> 5) & 31;
        int j  = i & 31;
        g_WxT[(gm * 32 + j) * WPITCH + k] = Wx[i];
    }
}

// ---------------- deg partials + fused h0!=0 probe ----------------
__global__ void __launch_bounds__(256) k_deg(
        const int4* __restrict__ src4,
        const float4* __restrict__ w4,
        const float4* __restrict__ h04) {
    int i = blockIdx.x * blockDim.x + threadIdx.x;
    if (i < N_EDGES / 4) {
        int4   s = src4[i];
        float4 w = w4[i];
        float* deg = G_DEGP + (blockIdx.x & (NP - 1)) * N_NODES;
        if ((unsigned)s.x < N_NODES) atomicAdd(&deg[s.x], w.x);
        if ((unsigned)s.y < N_NODES) atomicAdd(&deg[s.y], w.y);
        if ((unsigned)s.z < N_NODES) atomicAdd(&deg[s.z], w.z);
        if ((unsigned)s.w < N_NODES) atomicAdd(&deg[s.w], w.w);
    }
    if (i < N_NODES * 8) {
        float4 v = h04[i];
        if (v.x != 0.f || v.y != 0.f || v.z != 0.f || v.w != 0.f) *G_FLAG = 1;
    }
}

// ---------------- reduce partials -> dinv + pre-scale to fp16 ----------------
__global__ void __launch_bounds__(256) k_xs(
        const float4* __restrict__ x4,
        const float4* __restrict__ h04) {
    int i = blockIdx.x * blockDim.x + threadIdx.x;
    if (i < N_NODES * 8) {
        int node = i >> 3;
        int p = i & 7;
        float part = G_DEGP[p * N_NODES + node];
        part += __shfl_xor_sync(0xffffffffu, part, 1);
        part += __shfl_xor_sync(0xffffffffu, part, 2);
        part += __shfl_xor_sync(0xffffffffu, part, 4);
        float d = part;
        float di = d > 0.f ? rsqrtf(d) : 0.f;
        if (p == 0) g_dinv[node] = di;
        float4 v = x4[i];
        __half2 a = __floats2half2_rn(v.x * di, v.y * di);
        __half2 b = __floats2half2_rn(v.z * di, v.w * di);
        uint2 pk;
        pk.x = *(unsigned*)&a; pk.y = *(unsigned*)&b;
        ((uint2*)g_Xsh)[i] = pk;
        if (*G_FLAG) {
            float4 h = h04[i];
            __half2 c = __floats2half2_rn(h.x * di, h.y * di);
            __half2 e = __floats2half2_rn(h.z * di, h.w * di);
            uint2 ph;
            ph.x = *(unsigned*)&c; ph.y = *(unsigned*)&e;
            ((uint2*)g_h0sh)[i] = ph;
        }
    }
}

// ---------------- edge aggregation: LXh[dst] += w * Xsh[src]; fp16 gather + fp16x2 RED ----------------
__global__ void __launch_bounds__(256) k_edge(
        const int* __restrict__ src,
        const int* __restrict__ dst,
        const float* __restrict__ w) {
    int lane = threadIdx.x & 31;
    long long wid = (long long)(blockIdx.x * blockDim.x + threadIdx.x) >> 5;
    long long e = wid * 32 + lane;

    int s = 0, d = 0;
    float nv = 0.f;
    if (e < N_EDGES) {
        int ss = src[e];
        int dd = dst[e];
        if ((unsigned)ss < N_NODES && (unsigned)dd < N_NODES) {
            s = ss; d = dd; nv = w[e];
        }
    }
    int hf = *G_FLAG;
    int sub = lane >> 3;
    int q   = lane & 7;
    __half* lxh = G_LXH;
    __half* lhh = G_LHH;

    #pragma unroll
    for (int it = 0; it < 8; it++) {
        int srcLane = it * 4 + sub;
        int   si  = __shfl_sync(0xffffffffu, s, srcLane);
        int   di  = __shfl_sync(0xffffffffu, d, srcLane);
        float nvi = __shfl_sync(0xffffffffu, nv, srcLane);
        if (nvi != 0.f) {
            __half2 wv = __float2half2_rn(nvi);
            uint2 raw = __ldg((const uint2*)(g_Xsh + (size_t)si * HID + q * 4));
            __half2 p0 = __hmul2(*(__half2*)&raw.x, wv);
            __half2 p1 = __hmul2(*(__half2*)&raw.y, wv);
            asm volatile("red.global.add.noftz.v2.f16x2 [%0], {%1,%2};"
                         :: "l"(lxh + (size_t)di * HID + q * 4),
                            "r"(*(unsigned*)&p0), "r"(*(unsigned*)&p1)
                         : "memory");
            if (hf) {
                uint2 rh = __ldg((const uint2*)(g_h0sh + (size_t)si * HID + q * 4));
                __half2 q0 = __hmul2(*(__half2*)&rh.x, wv);
                __half2 q1 = __hmul2(*(__half2*)&rh.y, wv);
                asm volatile("red.global.add.noftz.v2.f16x2 [%0], {%1,%2};"
                             :: "l"(lhh + (size_t)di * HID + q * 4),
                                "r"(*(unsigned*)&q0), "r"(*(unsigned*)&q1)
                             : "memory");
            }
        }
    }
}

// helpers
__device__ __forceinline__ unsigned long long ffma2(
        unsigned long long a, unsigned long long bb, unsigned long long c) {
    unsigned long long r;
    asm("fma.rn.f32x2 %0, %1, %2, %3;" : "=l"(r) : "l"(a), "l"(bb), "l"(c));
    return r;
}
__device__ __forceinline__ float fold2(unsigned long long a) {
    float lo = __uint_as_float((unsigned)(a & 0xffffffffu));
    float hi = __uint_as_float((unsigned)(a >> 32));
    return lo + hi;
}
__device__ __forceinline__ float fast_sigmoid(float x) {
    return 1.f / (1.f + __expf(-x));
}
__device__ __forceinline__ float fast_tanh(float x) {
    float e2 = __expf(2.f * x);
    return __fdividef(e2 - 1.f, e2 + 1.f);
}

// ================= FAST gates kernel (h0 == 0): R13 shape + float4 prologue + fast tanh =================
#define TN 32
__global__ void __launch_bounds__(256) k_gates_fast(
        const float4* __restrict__ x4,
        const float* __restrict__ c0,
        const float* __restrict__ bx,
        const float* __restrict__ bh,
        const float* __restrict__ wc,
        const float* __restrict__ b,
        const float* __restrict__ Wl,   // [32][12]
        const float* __restrict__ bl,
        float* __restrict__ out) {
    if (*G_FLAG) return;

    __shared__ float sWt[256 * WPITCH];   // 34 KB
    __shared__ float sU[TN * 64];         // 8 KB
    __shared__ float sWl[HID * HOR];
    __shared__ float sbsum[4 * HID];
    __shared__ float swc[3 * HID];
    __shared__ float sbl[HOR];

    int tid = threadIdx.x;
    int nodeBase = blockIdx.x * TN;

    // prologue: flat float4 copy of pre-transposed weights (8704 floats = 2176 float4)
    for (int i = tid; i < 2176; i += 256)
        ((float4*)sWt)[i] = __ldg(((const float4*)g_WxT) + i);
    for (int i = tid; i < HID * HOR; i += 256) sWl[i] = Wl[i];
    if (tid < 4 * HID) sbsum[tid] = bx[tid] + bh[tid] + b[tid];
    if (tid < 3 * HID) swc[tid] = wc[tid];
    if (tid < HOR)     sbl[tid] = bl[tid];

    const uint2* lxh = (const uint2*)G_LXH;

    for (int i = tid; i < TN * 16; i += 256) {
        int n = i >> 4, m = (i >> 3) & 1, kq = i & 7;
        int node = nodeBase + n;
        float4 v = make_float4(0.f, 0.f, 0.f, 0.f);
        if (node < N_NODES) {
            if (m) {
                uint2 rw = lxh[node * 8 + kq];
                float2 a = __half22float2(*(__half2*)&rw.x);
                float2 bb = __half22float2(*(__half2*)&rw.y);
                float sc = -g_dinv[node];
                v = make_float4(a.x * sc, a.y * sc, bb.x * sc, bb.y * sc);
            } else {
                v = x4[node * 8 + kq];
            }
        }
        ((float4*)sU)[(n * 2 + m) * 8 + kq] = v;
    }
    __syncthreads();

    int warp = tid >> 5;
    int j = tid & 31;
    int nb = warp * 4;

    unsigned long long acc2[4][4];
    #pragma unroll
    for (int n = 0; n < 4; n++)
        #pragma unroll
        for (int g = 0; g < 4; g++) acc2[n][g] = 0ull;

    #pragma unroll
    for (int kk = 0; kk < 16; kk++) {
        unsigned long long wa[4], wb[4];
        #pragma unroll
        for (int g = 0; g < 4; g++) {
            wa[g] = *(const unsigned long long*)&sWt[((g * 2 + 0) * 32 + j) * WPITCH + 2 * kk];
            wb[g] = *(const unsigned long long*)&sWt[((g * 2 + 1) * 32 + j) * WPITCH + 2 * kk];
        }
        #pragma unroll
        for (int n = 0; n < 4; n++) {
            unsigned long long u0 = *(const unsigned long long*)&sU[(nb + n) * 64 + 2 * kk];
            unsigned long long u1 = *(const unsigned long long*)&sU[(nb + n) * 64 + 32 + 2 * kk];
            #pragma unroll
            for (int g = 0; g < 4; g++) {
                acc2[n][g] = ffma2(u0, wa[g], acc2[n][g]);
                acc2[n][g] = ffma2(u1, wb[g], acc2[n][g]);
            }
        }
    }

    float* oh = out;
    float* oH = out + (size_t)N_NODES * HOR;
    float* oC = oH + (size_t)N_NODES * HID;

    #pragma unroll
    for (int n = 0; n < 4; n++) {
        int node = nodeBase + nb + n;
        if (node < N_NODES) {
            float a0 = fold2(acc2[n][0]);
            float a1 = fold2(acc2[n][1]);
            float a2 = fold2(acc2[n][2]);
            float a3 = fold2(acc2[n][3]);
            float c0v = c0[node * HID + j];
            float preI = a0 + sbsum[0 * 32 + j] + swc[0 * 32 + j] * c0v;
            float preF = a1 + sbsum[1 * 32 + j] + swc[1 * 32 + j] * c0v;
            float preT = a2 + sbsum[2 * 32 + j];
            float I  = fast_sigmoid(preI);
            float Fg = fast_sigmoid(preF);
            float T  = fast_tanh(preT);
            float C  = Fg * c0v + I * T;
            float preO = a3 + sbsum[3 * 32 + j] + swc[2 * 32 + j] * C;
            float O  = fast_sigmoid(preO);
            float H  = O * fast_tanh(C);

            oH[node * HID + j] = H;
            oC[node * HID + j] = C;

            float rH = fmaxf(H, 0.f);
            float keep = 0.f;
            #pragma unroll
            for (int k = 0; k < 32; k++) {
                float rHk = __shfl_sync(0xffffffffu, rH, k);
                if (j < HOR) keep += rHk * sWl[k * HOR + j];
            }
            if (j < HOR) oh[node * HOR + j] = keep + sbl[j];
        }
    }
}

// ================= GENERIC gates kernel: only runs when h0 != 0 =================
#define GBLOCKS 592
__global__ void __launch_bounds__(256) k_gates_hf(
        const float4* __restrict__ x4,
        const float4* __restrict__ h04,
        const float* __restrict__ c0,
        const float* __restrict__ Wx,
        const float* __restrict__ bx,
        const float* __restrict__ Wh,
        const float* __restrict__ bh,
        const float* __restrict__ wc,
        const float* __restrict__ b,
        const float* __restrict__ Wl,
        const float* __restrict__ bl,
        float* __restrict__ out) {
    if (!*G_FLAG) return;

    __shared__ float sWx[8192];
    __shared__ float sU[16 * 4 * 32];
    __shared__ float sWl[HID * HOR];
    __shared__ float sbsum[4 * HID];
    __shared__ float swc[3 * HID];
    __shared__ float sbl[HOR];

    int tid = threadIdx.x;

    for (int i = tid; i < 8192; i += 256) sWx[i] = Wx[i];
    for (int i = tid; i < HID * HOR; i += 256) sWl[i] = Wl[i];
    if (tid < 4 * HID) sbsum[tid] = bx[tid] + bh[tid] + b[tid];
    if (tid < 3 * HID) swc[tid] = wc[tid];
    if (tid < HOR)     sbl[tid] = bl[tid];

    const uint2* lxh = (const uint2*)G_LXH;
    const uint2* lhh = (const uint2*)G_LHH;

    int ntiles = (N_NODES + 15) / 16;
    int warp = tid >> 5;
    int j = tid & 31;

    float* oh = out;
    float* oH = out + (size_t)N_NODES * HOR;
    float* oC = oH + (size_t)N_NODES * HID;

    for (int tile = blockIdx.x; tile < ntiles; tile += GBLOCKS) {
        int nodeBase = tile * 16;
        __syncthreads();
        for (int i = tid; i < 512; i += 256) {
            int n = i >> 5, m = (i >> 3) & 3, kq = i & 7;
            int node = nodeBase + n;
            float4 v = make_float4(0.f, 0.f, 0.f, 0.f);
            if (node < N_NODES) {
                if (m == 0) v = x4[node * 8 + kq];
                else if (m == 2) v = h04[node * 8 + kq];
                else {
                    uint2 rw = (m == 1) ? lxh[node * 8 + kq] : lhh[node * 8 + kq];
                    float2 a = __half22float2(*(__half2*)&rw.x);
                    float2 bb = __half22float2(*(__half2*)&rw.y);
                    float sc = -g_dinv[node];
                    v = make_float4(a.x * sc, a.y * sc, bb.x * sc, bb.y * sc);
                }
            }
            ((float4*)sU)[(n * 4 + m) * 8 + kq] = v;
        }
        __syncthreads();

        float acc[2][4];
        #pragma unroll
        for (int n = 0; n < 2; n++)
            #pragma unroll
            for (int g = 0; g < 4; g++) acc[n][g] = 0.f;

        int nb = warp * 2;
        #pragma unroll
        for (int k = 0; k < 32; k++) {
            float wa[4], wb[4], wha[4], whb[4];
            #pragma unroll
            for (int g = 0; g < 4; g++) {
                wa[g]  = sWx[g * 2048 +        k * 32 + j];
                wb[g]  = sWx[g * 2048 + 1024 + k * 32 + j];
                wha[g] = __ldg(&Wh[g * 2048 +        k * 32 + j]);
                whb[g] = __ldg(&Wh[g * 2048 + 1024 + k * 32 + j]);
            }
            #pragma unroll
            for (int n = 0; n < 2; n++) {
                float xv  = sU[((nb + n) * 4 + 0) * 32 + k];
                float lxv = sU[((nb + n) * 4 + 1) * 32 + k];
                float hv  = sU[((nb + n) * 4 + 2) * 32 + k];
                float lhv = sU[((nb + n) * 4 + 3) * 32 + k];
                #pragma unroll
                for (int g = 0; g < 4; g++)
                    acc[n][g] += xv * wa[g] + lxv * wb[g] + hv * wha[g] + lhv * whb[g];
            }
        }

        #pragma unroll
        for (int n = 0; n < 2; n++) {
            int node = nodeBase + nb + n;
            if (node < N_NODES) {
                float c0v = c0[node * HID + j];
                float preI = acc[n][0] + sbsum[0 * 32 + j] + swc[0 * 32 + j] * c0v;
                float preF = acc[n][1] + sbsum[1 * 32 + j] + swc[1 * 32 + j] * c0v;
                float preT = acc[n][2] + sbsum[2 * 32 + j];
                float I  = 1.f / (1.f + __expf(-preI));
                float Fg = 1.f / (1.f + __expf(-preF));
                float T  = tanhf(preT);
                float C  = Fg * c0v + I * T;
                float preO = acc[n][3] + sbsum[3 * 32 + j] + swc[2 * 32 + j] * C;
                float O  = 1.f / (1.f + __expf(-preO));
                float H  = O * tanhf(C);

                oH[node * HID + j] = H;
                oC[node * HID + j] = C;

                float rH = fmaxf(H, 0.f);
                float keep = 0.f;
                #pragma unroll
                for (int k = 0; k < 32; k++) {
                    float rHk = __shfl_sync(0xffffffffu, rH, k);
                    if (j < HOR) keep += rHk * sWl[k * HOR + j];
                }
                if (j < HOR) oh[node * HOR + j] = keep + sbl[j];
            }
        }
    }
}

// ---------------- launch ----------------
extern "C" void kernel_launch(void* const* d_in, const int* in_sizes, int n_in,
                              void* d_out, int out_size) {
    int iX, iEI, iEW, iWx, iBx, iWh, iBh, iWc, iB, iWl, iBl, iH0, iC0;
    if (n_in > 8 && in_sizes[8] == 2 * N_EDGES) {
        iWl = 0; iWh = 1; iWx = 2; iB = 3; iBl = 4; iBh = 5; iBx = 6;
        iC0 = 7; iEI = 8; iEW = 9; iH0 = 10; iWc = 11; iX = 12;
    } else {
        iX = 0; iEI = 1; iEW = 2; iWx = 3; iBx = 4; iWh = 5; iBh = 6;
        iWc = 7; iB = 8; iWl = 9; iBl = 10; iH0 = 11; iC0 = 12;
    }

    const float* x    = (const float*)d_in[iX];
    const int*   ei   = (const int*)d_in[iEI];     // int32 (JAX x64 off)
    const float* ew   = (const float*)d_in[iEW];
    const float* Wx   = (const float*)d_in[iWx];
    const float* bx   = (const float*)d_in[iBx];
    const float* Wh   = (const float*)d_in[iWh];
    const float* bh   = (const float*)d_in[iBh];
    const float* wc   = (const float*)d_in[iWc];
    const float* b    = (const float*)d_in[iB];
    const float* Wl   = (const float*)d_in[iWl];
    const float* bl   = (const float*)d_in[iBl];
    const float* h0   = (const float*)d_in[iH0];
    const float* c0   = (const float*)d_in[iC0];
    float*       out  = (float*)d_out;

    const int* src = ei;
    const int* dst = ei + N_EDGES;

    void* pZ;
    cudaGetSymbolAddress(&pZ, g_zbuf);
    cudaMemsetAsync(pZ, 0, Z_TOTAL * sizeof(float));

    k_prep<<<32, 256>>>(Wx);

    k_deg<<<(N_EDGES / 4 + 255) / 256, 256>>>(
        (const int4*)src, (const float4*)ew, (const float4*)h0);

    k_xs<<<(N_NODES * 8 + 255) / 256, 256>>>(
        (const float4*)x, (const float4*)h0);

    long long warps = (N_EDGES + 31) / 32;
    k_edge<<<(int)((warps * 32 + 255) / 256), 256>>>(src, dst, ew);

    k_gates_fast<<<(N_NODES + TN - 1) / TN, 256>>>(
        (const float4*)x, c0, bx, bh, wc, b, Wl, bl, out);
    k_gates_hf<<<GBLOCKS, 256>>>(
        (const float4*)x, (const float4*)h0, c0,
        Wx, bx, Wh, bh, wc, b, Wl, bl, out);
}